// round 2
// baseline (speedup 1.0000x reference)
#include <cuda_runtime.h>
#include <cstdint>

#define N_NODES 16384
#define N_EDGES 8192
#define C_DIM   256
#define NNZ_P   262144
#define SCALE   0.17677669529663687f   /* 1/sqrt(32) */

// ---------------- device scratch (no allocations allowed) ----------------
__device__ float g_QKV[(size_t)N_NODES * 3 * C_DIM];   // rows of 768: Q|K|V
__device__ float g_Xe[(size_t)N_EDGES * C_DIM];        // hyperedge mean features
__device__ float g_Ke[(size_t)N_EDGES * C_DIM];        // Xe @ Wke + bke
__device__ float g_cnt[N_EDGES];

// ---------------- generic GEMM: Out[m, coff+n] = A[m,:] @ W[:,n] + b[n] ----
// A: [M,256] row-major, W: [256,256] row-major (in,out). BM=BN=64, BK=16.
__global__ void __launch_bounds__(256)
gemm_bias_kernel(const float* __restrict__ A, const float* __restrict__ W,
                 const float* __restrict__ bias, float* __restrict__ Out,
                 int ldo, int coff)
{
    __shared__ float As[16][68];   // As[k][m]
    __shared__ float Ws[16][68];   // Ws[k][n]
    const int tid = threadIdx.x;
    const int bm = blockIdx.x * 64;
    const int bn = blockIdx.y * 64;
    const int ti = tid >> 4;          // 0..15
    const int tj = tid & 15;          // 0..15
    const int ra = tid >> 2;          // 0..63 (A row)
    const int ka = (tid & 3) << 2;    // 0,4,8,12
    const int kw = tid >> 4;          // 0..15 (W k)
    const int cw = (tid & 15) << 2;   // 0..60

    float acc[4][4] = {};
    for (int k0 = 0; k0 < 256; k0 += 16) {
        float4 a = *(const float4*)(A + (size_t)(bm + ra) * 256 + k0 + ka);
        As[ka + 0][ra] = a.x; As[ka + 1][ra] = a.y;
        As[ka + 2][ra] = a.z; As[ka + 3][ra] = a.w;
        float4 w = *(const float4*)(W + (size_t)(k0 + kw) * 256 + bn + cw);
        *(float4*)&Ws[kw][cw] = w;
        __syncthreads();
#pragma unroll
        for (int k = 0; k < 16; k++) {
            float4 av = *(const float4*)&As[k][ti * 4];
            float4 wv = *(const float4*)&Ws[k][tj * 4];
            float a4[4] = {av.x, av.y, av.z, av.w};
            float w4[4] = {wv.x, wv.y, wv.z, wv.w};
#pragma unroll
            for (int i = 0; i < 4; i++)
#pragma unroll
                for (int j = 0; j < 4; j++)
                    acc[i][j] = fmaf(a4[i], w4[j], acc[i][j]);
        }
        __syncthreads();
    }
    float4 b = *(const float4*)(bias + bn + tj * 4);
#pragma unroll
    for (int i = 0; i < 4; i++) {
        float4 o;
        o.x = acc[i][0] + b.x; o.y = acc[i][1] + b.y;
        o.z = acc[i][2] + b.z; o.w = acc[i][3] + b.w;
        *(float4*)(Out + (size_t)(bm + ti * 4 + i) * ldo + coff + bn + tj * 4) = o;
    }
}

// ---------------- segment sum (atomics) ----------------
__global__ void __launch_bounds__(256)
seg_accum_kernel(const float* __restrict__ X, const int* __restrict__ v_ids,
                 const int* __restrict__ e_ids)
{
    int t = blockIdx.x * 256 + threadIdx.x;   // NNZ * 64 threads
    int pair = t >> 6;
    int c4 = t & 63;
    if (pair >= NNZ_P) return;
    int v = v_ids[pair];
    int e = e_ids[pair];
    float4 x = ((const float4*)(X + (size_t)v * 256))[c4];
    float* dst = g_Xe + (size_t)e * 256 + c4 * 4;
    atomicAdd(dst + 0, x.x);
    atomicAdd(dst + 1, x.y);
    atomicAdd(dst + 2, x.z);
    atomicAdd(dst + 3, x.w);
    if (c4 == 0) atomicAdd(&g_cnt[e], 1.0f);
}

__global__ void __launch_bounds__(256)
seg_finalize_kernel()
{
    int t = blockIdx.x * 256 + threadIdx.x;   // E * 64
    int e = t >> 6;
    int c4 = t & 63;
    float inv = 1.0f / fmaxf(g_cnt[e], 1.0f);
    float4* p = (float4*)(g_Xe + (size_t)e * 256) + c4;
    float4 x = *p;
    x.x *= inv; x.y *= inv; x.z *= inv; x.w *= inv;
    *p = x;
}

// ---------------- per-node 8x8 head attention -> writes X_node into out ----
__device__ __forceinline__ float warp_sum(float v) {
#pragma unroll
    for (int off = 16; off; off >>= 1) v += __shfl_xor_sync(0xffffffffu, v, off);
    return v;
}

__global__ void __launch_bounds__(256)
node_attn_kernel(float* __restrict__ out)
{
    int warp = (blockIdx.x * 256 + threadIdx.x) >> 5;
    int lane = threadIdx.x & 31;
    if (warp >= N_NODES) return;
    const float* row = g_QKV + (size_t)warp * 768;
    float q[8], k[8], v[8];
#pragma unroll
    for (int h = 0; h < 8; h++) {
        q[h] = row[h * 32 + lane];
        k[h] = row[256 + h * 32 + lane];
        v[h] = row[512 + h * 32 + lane];
    }
    float s[8][8];
#pragma unroll
    for (int h = 0; h < 8; h++)
#pragma unroll
        for (int g = 0; g < 8; g++)
            s[h][g] = warp_sum(q[h] * k[g]) * SCALE;

#pragma unroll
    for (int h = 0; h < 8; h++) {
        float m = s[h][0];
#pragma unroll
        for (int g = 1; g < 8; g++) m = fmaxf(m, s[h][g]);
        float sum = 0.f;
#pragma unroll
        for (int g = 0; g < 8; g++) { s[h][g] = __expf(s[h][g] - m); sum += s[h][g]; }
        float inv = 1.0f / sum;
        float o = 0.f;
#pragma unroll
        for (int g = 0; g < 8; g++) o = fmaf(s[h][g] * inv, v[g], o);
        out[(size_t)warp * 256 + h * 32 + lane] = o;
    }
}

// ---------------- flash attention over hyperedges --------------------------
// per block: TM=64 queries; loop E in TN=64 key tiles; D=256; fp32.
// thread grids: phase-S 16x16 (4x4 frag), softmax/PV: warp wrp owns rows
// wrp*8..+7, lane owns cols {lane*4..+3, 128+lane*4..+3}.
#define QS_STRIDE 257
#define KS_STRIDE 257
#define VS_STRIDE 260
#define PS_STRIDE 65
#define SMEM_FLASH ((64*QS_STRIDE + 64*KS_STRIDE + 64*VS_STRIDE + 64*PS_STRIDE) * 4)

__global__ void __launch_bounds__(256, 1)
edge_attn_kernel(float* __restrict__ out)
{
    extern __shared__ float sm[];
    float* Qs = sm;                          // [64][257]
    float* Ks = Qs + 64 * QS_STRIDE;         // [64][257]
    float* Vs = Ks + 64 * KS_STRIDE;         // [64][260]
    float* Ps = Vs + 64 * VS_STRIDE;         // [64][65]

    const int tid  = threadIdx.x;
    const int lane = tid & 31;
    const int wrp  = tid >> 5;               // 0..7
    const int n0   = blockIdx.x * 64;
    const int ti   = tid >> 4;               // phase-S row grp
    const int tj   = tid & 15;               // phase-S col grp

    // load Q tile [64][256] from g_QKV (Q at col offset 0), row-major smem
    for (int it = 0; it < 16; it++) {
        int idx = it * 256 + tid;            // float4 index
        int m = idx >> 6;
        int k4 = idx & 63;
        float4 qv = *(const float4*)(g_QKV + (size_t)(n0 + m) * 768 + k4 * 4);
        float* d = Qs + m * QS_STRIDE + k4 * 4;
        d[0] = qv.x; d[1] = qv.y; d[2] = qv.z; d[3] = qv.w;
    }

    float O[8][8];
#pragma unroll
    for (int i = 0; i < 8; i++)
#pragma unroll
        for (int j = 0; j < 8; j++) O[i][j] = 0.f;
    float mrow[8], lrow[8];
#pragma unroll
    for (int i = 0; i < 8; i++) { mrow[i] = -1e30f; lrow[i] = 0.f; }

    for (int e0 = 0; e0 < N_EDGES; e0 += 64) {
        __syncthreads();   // previous tile's consumers done; Q visible on iter 0
        // load K tile (Ke) and V tile (Xe), both [64][256]
        for (int it = 0; it < 16; it++) {
            int idx = it * 256 + tid;
            int r = idx >> 6;
            int k4 = idx & 63;
            float4 kv = *(const float4*)(g_Ke + (size_t)(e0 + r) * 256 + k4 * 4);
            float* kd = Ks + r * KS_STRIDE + k4 * 4;
            kd[0] = kv.x; kd[1] = kv.y; kd[2] = kv.z; kd[3] = kv.w;
            float4 vv = *(const float4*)(g_Xe + (size_t)(e0 + r) * 256 + k4 * 4);
            *(float4*)(Vs + r * VS_STRIDE + k4 * 4) = vv;
        }
        __syncthreads();

        // ---- phase S: S[64][64] = Q @ K^T ----
        float acc[4][4] = {};
        const float* qb = Qs + ti * 4 * QS_STRIDE;
        const float* kb = Ks + tj * 4 * KS_STRIDE;
#pragma unroll 4
        for (int k = 0; k < 256; k++) {
            float a0 = qb[k];
            float a1 = qb[QS_STRIDE + k];
            float a2 = qb[2 * QS_STRIDE + k];
            float a3 = qb[3 * QS_STRIDE + k];
            float b0 = kb[k];
            float b1 = kb[KS_STRIDE + k];
            float b2 = kb[2 * KS_STRIDE + k];
            float b3 = kb[3 * KS_STRIDE + k];
            acc[0][0] = fmaf(a0, b0, acc[0][0]); acc[0][1] = fmaf(a0, b1, acc[0][1]);
            acc[0][2] = fmaf(a0, b2, acc[0][2]); acc[0][3] = fmaf(a0, b3, acc[0][3]);
            acc[1][0] = fmaf(a1, b0, acc[1][0]); acc[1][1] = fmaf(a1, b1, acc[1][1]);
            acc[1][2] = fmaf(a1, b2, acc[1][2]); acc[1][3] = fmaf(a1, b3, acc[1][3]);
            acc[2][0] = fmaf(a2, b0, acc[2][0]); acc[2][1] = fmaf(a2, b1, acc[2][1]);
            acc[2][2] = fmaf(a2, b2, acc[2][2]); acc[2][3] = fmaf(a2, b3, acc[2][3]);
            acc[3][0] = fmaf(a3, b0, acc[3][0]); acc[3][1] = fmaf(a3, b1, acc[3][1]);
            acc[3][2] = fmaf(a3, b2, acc[3][2]); acc[3][3] = fmaf(a3, b3, acc[3][3]);
        }
#pragma unroll
        for (int u = 0; u < 4; u++)
#pragma unroll
            for (int v = 0; v < 4; v++)
                Ps[(ti * 4 + u) * PS_STRIDE + tj * 4 + v] = acc[u][v];
        __syncthreads();

        // ---- online softmax: warp wrp handles rows wrp*8..+7 ----
#pragma unroll
        for (int i = 0; i < 8; i++) {
            int r = wrp * 8 + i;
            float s0 = Ps[r * PS_STRIDE + lane] * SCALE;
            float s1 = Ps[r * PS_STRIDE + 32 + lane] * SCALE;
            float mx = fmaxf(s0, s1);
#pragma unroll
            for (int off = 16; off; off >>= 1)
                mx = fmaxf(mx, __shfl_xor_sync(0xffffffffu, mx, off));
            float mnew = fmaxf(mrow[i], mx);
            float p0 = __expf(s0 - mnew);
            float p1 = __expf(s1 - mnew);
            float ps = warp_sum(p0 + p1);
            float alpha = __expf(mrow[i] - mnew);
            lrow[i] = lrow[i] * alpha + ps;
            mrow[i] = mnew;
            Ps[r * PS_STRIDE + lane] = p0;
            Ps[r * PS_STRIDE + 32 + lane] = p1;
#pragma unroll
            for (int j = 0; j < 8; j++) O[i][j] *= alpha;
        }
        // no sync needed: each warp reads only the P rows it just wrote

        // ---- PV: O += P @ V ----
        const float* pb = Ps + wrp * 8 * PS_STRIDE;
        for (int j = 0; j < 64; j++) {
            float4 v0 = *(const float4*)(Vs + j * VS_STRIDE + lane * 4);
            float4 v1 = *(const float4*)(Vs + j * VS_STRIDE + 128 + lane * 4);
#pragma unroll
            for (int i = 0; i < 8; i++) {
                float p = pb[i * PS_STRIDE + j];
                O[i][0] = fmaf(p, v0.x, O[i][0]);
                O[i][1] = fmaf(p, v0.y, O[i][1]);
                O[i][2] = fmaf(p, v0.z, O[i][2]);
                O[i][3] = fmaf(p, v0.w, O[i][3]);
                O[i][4] = fmaf(p, v1.x, O[i][4]);
                O[i][5] = fmaf(p, v1.y, O[i][5]);
                O[i][6] = fmaf(p, v1.z, O[i][6]);
                O[i][7] = fmaf(p, v1.w, O[i][7]);
            }
        }
    }

    // epilogue: out = relu(X_node (already in out) + O/l)
#pragma unroll
    for (int i = 0; i < 8; i++) {
        size_t r = (size_t)(n0 + wrp * 8 + i);
        float inv = 1.0f / lrow[i];
        float* p0 = out + r * 256 + lane * 4;
        float* p1 = p0 + 128;
        float4 a = *(float4*)p0;
        float4 b = *(float4*)p1;
        a.x = fmaxf(a.x + O[i][0] * inv, 0.f);
        a.y = fmaxf(a.y + O[i][1] * inv, 0.f);
        a.z = fmaxf(a.z + O[i][2] * inv, 0.f);
        a.w = fmaxf(a.w + O[i][3] * inv, 0.f);
        b.x = fmaxf(b.x + O[i][4] * inv, 0.f);
        b.y = fmaxf(b.y + O[i][5] * inv, 0.f);
        b.z = fmaxf(b.z + O[i][6] * inv, 0.f);
        b.w = fmaxf(b.w + O[i][7] * inv, 0.f);
        *(float4*)p0 = a;
        *(float4*)p1 = b;
    }
}

// ---------------- launch ----------------
extern "C" void kernel_launch(void* const* d_in, const int* in_sizes, int n_in,
                              void* d_out, int out_size)
{
    (void)in_sizes; (void)n_in; (void)out_size;
    const float* X    = (const float*)d_in[0];
    const int*   v_ids = (const int*)d_in[1];
    const int*   e_ids = (const int*)d_in[2];
    const float* Wq = (const float*)d_in[3];
    const float* bq = (const float*)d_in[4];
    const float* Wk = (const float*)d_in[5];
    const float* bk = (const float*)d_in[6];
    const float* Wv = (const float*)d_in[7];
    const float* bv = (const float*)d_in[8];
    const float* Wke = (const float*)d_in[9];
    const float* bke = (const float*)d_in[10];
    float* out = (float*)d_out;

    void *pXe, *pcnt, *pQKV, *pKe;
    cudaGetSymbolAddress(&pXe, g_Xe);
    cudaGetSymbolAddress(&pcnt, g_cnt);
    cudaGetSymbolAddress(&pQKV, g_QKV);
    cudaGetSymbolAddress(&pKe, g_Ke);

    cudaMemsetAsync(pXe, 0, (size_t)N_EDGES * C_DIM * sizeof(float));
    cudaMemsetAsync(pcnt, 0, (size_t)N_EDGES * sizeof(float));

    dim3 gq(N_NODES / 64, 4);
    gemm_bias_kernel<<<gq, 256>>>(X, Wq, bq, (float*)pQKV, 768, 0);
    gemm_bias_kernel<<<gq, 256>>>(X, Wk, bk, (float*)pQKV, 768, 256);
    gemm_bias_kernel<<<gq, 256>>>(X, Wv, bv, (float*)pQKV, 768, 512);

    seg_accum_kernel<<<(NNZ_P * 64) / 256, 256>>>(X, v_ids, e_ids);
    seg_finalize_kernel<<<(N_EDGES * 64) / 256, 256>>>();

    gemm_bias_kernel<<<dim3(N_EDGES / 64, 4), 256>>>((const float*)pXe, Wke, bke,
                                                     (float*)pKe, 256, 0);

    node_attn_kernel<<<(N_NODES * 32) / 256, 256>>>(out);

    cudaFuncSetAttribute(edge_attn_kernel,
                         cudaFuncAttributeMaxDynamicSharedMemorySize, SMEM_FLASH);
    edge_attn_kernel<<<N_NODES / 64, 256, SMEM_FLASH>>>(out);
}

// round 4
// speedup vs baseline: 5.8567x; 5.8567x over previous
#include <cuda_runtime.h>
#include <cuda_bf16.h>
#include <cstdint>

#define N_NODES 16384
#define N_EDGES 8192
#define C_DIM   256
#define NNZ_P   262144
#define SCALE   0.17677669529663687f   /* 1/sqrt(32) */

// ---------------- device scratch ----------------
__device__ float g_QKV[(size_t)N_NODES * 3 * C_DIM];   // rows of 768: Q|K|V (fp32)
__device__ float g_Xe[(size_t)N_EDGES * C_DIM];        // hyperedge mean features
__device__ float g_Ke[(size_t)N_EDGES * C_DIM];        // Xe @ Wke + bke (fp32)
__device__ float g_cnt[N_EDGES];
__device__ __nv_bfloat16 g_Qb[(size_t)N_NODES * C_DIM];    // Q bf16 row-major
__device__ __nv_bfloat16 g_Keb[(size_t)N_EDGES * C_DIM];   // Ke bf16 row-major
__device__ __nv_bfloat16 g_XeTb[(size_t)C_DIM * N_EDGES];  // Xe^T bf16 [C][E]

// ================= helpers =================
__device__ __forceinline__ uint32_t smem_to_u32(const void* p) {
    uint32_t a;
    asm("{ .reg .u64 t; cvta.to.shared.u64 t, %1; cvt.u32.u64 %0, t; }" : "=r"(a) : "l"(p));
    return a;
}
#define CVT_BF16X2_F32(result, a, b) \
    asm("cvt.rn.satfinite.bf16x2.f32 %0, %1, %2;" : "=r"(result) : "f"(b), "f"(a))

__device__ __forceinline__ void cp16(uint32_t dst, const void* src) {
    asm volatile("cp.async.cg.shared.global [%0], [%1], 16;" :: "r"(dst), "l"(src));
}
#define CP_COMMIT() asm volatile("cp.async.commit_group;" ::: "memory")
#define CP_WAIT0()  asm volatile("cp.async.wait_group 0;" ::: "memory")

__device__ __forceinline__ void ldsm4(uint32_t* r, uint32_t addr) {
    asm volatile("ldmatrix.sync.aligned.m8n8.x4.shared.b16 {%0,%1,%2,%3}, [%4];"
        : "=r"(r[0]), "=r"(r[1]), "=r"(r[2]), "=r"(r[3]) : "r"(addr));
}
__device__ __forceinline__ void mma16816(float* d, const uint32_t* a, uint32_t b0, uint32_t b1) {
    asm volatile("mma.sync.aligned.m16n8k16.row.col.f32.bf16.bf16.f32 "
        "{%0,%1,%2,%3}, {%4,%5,%6,%7}, {%8,%9}, {%0,%1,%2,%3};"
        : "+f"(d[0]), "+f"(d[1]), "+f"(d[2]), "+f"(d[3])
        : "r"(a[0]), "r"(a[1]), "r"(a[2]), "r"(a[3]), "r"(b0), "r"(b1));
}

// ---------------- generic GEMM (fp32, optional bf16 side-output) ----------
__global__ void __launch_bounds__(256)
gemm_bias_kernel(const float* __restrict__ A, const float* __restrict__ W,
                 const float* __restrict__ bias, float* __restrict__ Out,
                 int ldo, int coff, __nv_bfloat16* __restrict__ outb)
{
    __shared__ float As[16][68];
    __shared__ float Ws[16][68];
    const int tid = threadIdx.x;
    const int bm = blockIdx.x * 64;
    const int bn = blockIdx.y * 64;
    const int ti = tid >> 4;
    const int tj = tid & 15;
    const int ra = tid >> 2;
    const int ka = (tid & 3) << 2;
    const int kw = tid >> 4;
    const int cw = (tid & 15) << 2;

    float acc[4][4] = {};
    for (int k0 = 0; k0 < 256; k0 += 16) {
        float4 a = *(const float4*)(A + (size_t)(bm + ra) * 256 + k0 + ka);
        As[ka + 0][ra] = a.x; As[ka + 1][ra] = a.y;
        As[ka + 2][ra] = a.z; As[ka + 3][ra] = a.w;
        float4 w = *(const float4*)(W + (size_t)(k0 + kw) * 256 + bn + cw);
        *(float4*)&Ws[kw][cw] = w;
        __syncthreads();
#pragma unroll
        for (int k = 0; k < 16; k++) {
            float4 av = *(const float4*)&As[k][ti * 4];
            float4 wv = *(const float4*)&Ws[k][tj * 4];
            float a4[4] = {av.x, av.y, av.z, av.w};
            float w4[4] = {wv.x, wv.y, wv.z, wv.w};
#pragma unroll
            for (int i = 0; i < 4; i++)
#pragma unroll
                for (int j = 0; j < 4; j++)
                    acc[i][j] = fmaf(a4[i], w4[j], acc[i][j]);
        }
        __syncthreads();
    }
    float4 b = *(const float4*)(bias + bn + tj * 4);
#pragma unroll
    for (int i = 0; i < 4; i++) {
        float4 o;
        o.x = acc[i][0] + b.x; o.y = acc[i][1] + b.y;
        o.z = acc[i][2] + b.z; o.w = acc[i][3] + b.w;
        *(float4*)(Out + (size_t)(bm + ti * 4 + i) * ldo + coff + bn + tj * 4) = o;
        if (outb) {
            uint32_t lo, hi;
            CVT_BF16X2_F32(lo, o.x, o.y);
            CVT_BF16X2_F32(hi, o.z, o.w);
            *(uint2*)(outb + (size_t)(bm + ti * 4 + i) * 256 + bn + tj * 4) = make_uint2(lo, hi);
        }
    }
}

// ---------------- segment sum (atomics) ----------------
__global__ void __launch_bounds__(256)
seg_accum_kernel(const float* __restrict__ X, const int* __restrict__ v_ids,
                 const int* __restrict__ e_ids)
{
    int t = blockIdx.x * 256 + threadIdx.x;
    int pair = t >> 6;
    int c4 = t & 63;
    if (pair >= NNZ_P) return;
    int v = v_ids[pair];
    int e = e_ids[pair];
    float4 x = ((const float4*)(X + (size_t)v * 256))[c4];
    float* dst = g_Xe + (size_t)e * 256 + c4 * 4;
    atomicAdd(dst + 0, x.x);
    atomicAdd(dst + 1, x.y);
    atomicAdd(dst + 2, x.z);
    atomicAdd(dst + 3, x.w);
    if (c4 == 0) atomicAdd(&g_cnt[e], 1.0f);
}

__global__ void __launch_bounds__(256)
seg_finalize_kernel()
{
    int t = blockIdx.x * 256 + threadIdx.x;
    int e = t >> 6;
    int c4 = t & 63;
    float inv = 1.0f / fmaxf(g_cnt[e], 1.0f);
    float4* p = (float4*)(g_Xe + (size_t)e * 256) + c4;
    float4 x = *p;
    x.x *= inv; x.y *= inv; x.z *= inv; x.w *= inv;
    *p = x;
}

// ---------------- Xe transpose -> bf16 [C][E]; also Ke row-major bf16 ------
__global__ void __launch_bounds__(256)
xe_transpose_kernel()
{
    __shared__ float t[64][65];
    int e0 = blockIdx.x * 64;
    int c0 = blockIdx.y * 64;
    int tid = threadIdx.x;
#pragma unroll
    for (int it = 0; it < 4; it++) {
        int idx = it * 256 + tid;
        int e = idx >> 4;
        int c4 = idx & 15;
        float4 v = *(const float4*)(g_Xe + (size_t)(e0 + e) * 256 + c0 + c4 * 4);
        t[e][c4 * 4 + 0] = v.x; t[e][c4 * 4 + 1] = v.y;
        t[e][c4 * 4 + 2] = v.z; t[e][c4 * 4 + 3] = v.w;
    }
    __syncthreads();
#pragma unroll
    for (int it = 0; it < 4; it++) {
        int idx = it * 256 + tid;
        int c = idx >> 4;
        int e4 = idx & 15;
        uint32_t lo, hi;
        CVT_BF16X2_F32(lo, t[e4 * 4 + 0][c], t[e4 * 4 + 1][c]);
        CVT_BF16X2_F32(hi, t[e4 * 4 + 2][c], t[e4 * 4 + 3][c]);
        *(uint2*)(g_XeTb + (size_t)(c0 + c) * N_EDGES + e0 + e4 * 4) = make_uint2(lo, hi);
    }
}

// ---------------- per-node 8x8 head attention ----------------
__device__ __forceinline__ float warp_sum(float v) {
#pragma unroll
    for (int off = 16; off; off >>= 1) v += __shfl_xor_sync(0xffffffffu, v, off);
    return v;
}

__global__ void __launch_bounds__(256)
node_attn_kernel(float* __restrict__ out)
{
    int warp = (blockIdx.x * 256 + threadIdx.x) >> 5;
    int lane = threadIdx.x & 31;
    if (warp >= N_NODES) return;
    const float* row = g_QKV + (size_t)warp * 768;
    float q[8], k[8], v[8];
#pragma unroll
    for (int h = 0; h < 8; h++) {
        q[h] = row[h * 32 + lane];
        k[h] = row[256 + h * 32 + lane];
        v[h] = row[512 + h * 32 + lane];
    }
    float s[8][8];
#pragma unroll
    for (int h = 0; h < 8; h++)
#pragma unroll
        for (int g = 0; g < 8; g++)
            s[h][g] = warp_sum(q[h] * k[g]) * SCALE;

#pragma unroll
    for (int h = 0; h < 8; h++) {
        float m = s[h][0];
#pragma unroll
        for (int g = 1; g < 8; g++) m = fmaxf(m, s[h][g]);
        float sum = 0.f;
#pragma unroll
        for (int g = 0; g < 8; g++) { s[h][g] = __expf(s[h][g] - m); sum += s[h][g]; }
        float inv = 1.0f / sum;
        float o = 0.f;
#pragma unroll
        for (int g = 0; g < 8; g++) o = fmaf(s[h][g] * inv, v[g], o);
        out[(size_t)warp * 256 + h * 32 + lane] = o;
    }
}

// ================= mma.sync bf16 flash attention over hyperedges ===========
// 128 queries/CTA (8 warps x 16 rows), TN=64 keys/iter, 128 iters, D=256.
// S = Q*Ke^T (k=256), register softmax (no max-sub: |score|<~2),
// P stays in registers as A-fragments; O[16x256] per warp in registers.
#define TM    128
#define TN    64
#define NITER (N_EDGES / TN)
#define QST   264    /* padded bf16 row stride: 528B -> conflict-free ldmatrix */
#define KST   264
#define VST   72     /* 144B */
#define SM_Q  0
#define SM_K0 67584
#define SM_K1 (SM_K0 + 33792)
#define SM_V0 (SM_K1 + 33792)
#define SM_V1 (SM_V0 + 36864)
#define SMEM_ATT (SM_V1 + 36864)   /* 208896 bytes */

__global__ void __launch_bounds__(256, 1)
edge_attn_mma_kernel(float* __restrict__ out)
{
    extern __shared__ char sm[];
    const uint32_t smem_base = smem_to_u32(sm);
    const int tid  = threadIdx.x;
    const int lane = tid & 31;
    const int wid  = tid >> 5;
    const int n0   = blockIdx.x * TM;
    const int m0   = wid * 16;

    // ---- prologue: Q tile + K/V tile 0 via cp.async ----
#pragma unroll
    for (int it = 0; it < 16; it++) {
        int idx = it * 256 + tid;
        int r = idx >> 5, ch = idx & 31;
        cp16(smem_base + SM_Q + (uint32_t)(r * QST + ch * 8) * 2,
             g_Qb + (size_t)(n0 + r) * 256 + ch * 8);
    }
#pragma unroll
    for (int it = 0; it < 8; it++) {
        int idx = it * 256 + tid;
        int e = idx >> 5, ch = idx & 31;
        cp16(smem_base + SM_K0 + (uint32_t)(e * KST + ch * 8) * 2,
             g_Keb + (size_t)e * 256 + ch * 8);
        int c = idx >> 3, vch = idx & 7;
        cp16(smem_base + SM_V0 + (uint32_t)(c * VST + vch * 8) * 2,
             g_XeTb + (size_t)c * N_EDGES + vch * 8);
    }
    CP_COMMIT();
    CP_WAIT0();
    __syncthreads();

    // per-thread ldmatrix address patterns
    const uint32_t a_base = smem_base + SM_Q +
        (uint32_t)((m0 + (lane & 15)) * QST + ((lane >> 4) << 3)) * 2;
    const uint32_t b_row    = (uint32_t)(((lane >> 4) << 3) + (lane & 7));
    const uint32_t b_coloff = (uint32_t)(((lane >> 3) & 1) << 3);
    const uint32_t kfrag_base[2] = {
        smem_base + SM_K0 + (b_row * KST + b_coloff) * 2,
        smem_base + SM_K1 + (b_row * KST + b_coloff) * 2 };
    const uint32_t vfrag_base[2] = {
        smem_base + SM_V0 + (b_row * VST + b_coloff) * 2,
        smem_base + SM_V1 + (b_row * VST + b_coloff) * 2 };

    float O[32][4];
#pragma unroll
    for (int j = 0; j < 32; j++)
#pragma unroll
        for (int q = 0; q < 4; q++) O[j][q] = 0.f;
    float lacc0 = 0.f, lacc1 = 0.f;

    for (int i = 0; i < NITER; i++) {
        const int b = i & 1;
        // prefetch next K/V tile into the other buffer
        if (i + 1 < NITER) {
            const int e0n = (i + 1) * TN;
            const uint32_t kb = smem_base + (b ? SM_K0 : SM_K1);
            const uint32_t vb = smem_base + (b ? SM_V0 : SM_V1);
#pragma unroll
            for (int it = 0; it < 8; it++) {
                int idx = it * 256 + tid;
                int e = idx >> 5, ch = idx & 31;
                cp16(kb + (uint32_t)(e * KST + ch * 8) * 2,
                     g_Keb + (size_t)(e0n + e) * 256 + ch * 8);
                int c = idx >> 3, vch = idx & 7;
                cp16(vb + (uint32_t)(c * VST + vch * 8) * 2,
                     g_XeTb + (size_t)c * N_EDGES + e0n + vch * 8);
            }
            CP_COMMIT();
        }

        // ---- S = Q * Ke^T : 16x64, k=256 ----
        float s[8][4];
#pragma unroll
        for (int j = 0; j < 8; j++)
#pragma unroll
            for (int q = 0; q < 4; q++) s[j][q] = 0.f;
        const uint32_t kb_ = kfrag_base[b];
#pragma unroll
        for (int k0 = 0; k0 < 256; k0 += 16) {
            uint32_t a[4];
            ldsm4(a, a_base + (uint32_t)k0 * 2);
#pragma unroll
            for (int jp = 0; jp < 4; jp++) {
                uint32_t bb[4];
                ldsm4(bb, kb_ + (uint32_t)(jp * 16 * KST + k0) * 2);
                mma16816(s[2 * jp],     a, bb[0], bb[1]);
                mma16816(s[2 * jp + 1], a, bb[2], bb[3]);
            }
        }

        // ---- softmax (no max-sub; scores bounded) ----
        float part0 = 0.f, part1 = 0.f;
#pragma unroll
        for (int j = 0; j < 8; j++) {
            s[j][0] = __expf(s[j][0] * SCALE);
            s[j][1] = __expf(s[j][1] * SCALE);
            s[j][2] = __expf(s[j][2] * SCALE);
            s[j][3] = __expf(s[j][3] * SCALE);
            part0 += s[j][0] + s[j][1];
            part1 += s[j][2] + s[j][3];
        }
        part0 += __shfl_xor_sync(0xffffffffu, part0, 1);
        part0 += __shfl_xor_sync(0xffffffffu, part0, 2);
        part1 += __shfl_xor_sync(0xffffffffu, part1, 1);
        part1 += __shfl_xor_sync(0xffffffffu, part1, 2);
        lacc0 += part0;
        lacc1 += part1;

        // ---- O += P * V (P in regs as A-fragments) ----
        const uint32_t vb_ = vfrag_base[b];
#pragma unroll
        for (int kb = 0; kb < 4; kb++) {
            uint32_t a[4];
            CVT_BF16X2_F32(a[0], s[2 * kb][0],     s[2 * kb][1]);
            CVT_BF16X2_F32(a[1], s[2 * kb][2],     s[2 * kb][3]);
            CVT_BF16X2_F32(a[2], s[2 * kb + 1][0], s[2 * kb + 1][1]);
            CVT_BF16X2_F32(a[3], s[2 * kb + 1][2], s[2 * kb + 1][3]);
#pragma unroll
            for (int jp = 0; jp < 16; jp++) {
                uint32_t bb[4];
                ldsm4(bb, vb_ + (uint32_t)(jp * 16 * VST + kb * 16) * 2);
                mma16816(O[2 * jp],     a, bb[0], bb[1]);
                mma16816(O[2 * jp + 1], a, bb[2], bb[3]);
            }
        }

        if (i + 1 < NITER) CP_WAIT0();
        __syncthreads();
    }

    // ---- epilogue: out = relu(X_node + O/l) ----
    const int g = lane >> 2;
    const int ti = lane & 3;
    const float inv0 = 1.0f / lacc0;
    const float inv1 = 1.0f / lacc1;
    const size_t row0 = (size_t)(n0 + m0 + g);
    const size_t row1 = row0 + 8;
#pragma unroll
    for (int j = 0; j < 32; j++) {
        int col = 8 * j + 2 * ti;
        float2* p0 = (float2*)(out + row0 * 256 + col);
        float2 v0 = *p0;
        v0.x = fmaxf(v0.x + O[j][0] * inv0, 0.f);
        v0.y = fmaxf(v0.y + O[j][1] * inv0, 0.f);
        *p0 = v0;
        float2* p1 = (float2*)(out + row1 * 256 + col);
        float2 v1 = *p1;
        v1.x = fmaxf(v1.x + O[j][2] * inv1, 0.f);
        v1.y = fmaxf(v1.y + O[j][3] * inv1, 0.f);
        *p1 = v1;
    }
}

// ---------------- launch ----------------
extern "C" void kernel_launch(void* const* d_in, const int* in_sizes, int n_in,
                              void* d_out, int out_size)
{
    (void)in_sizes; (void)n_in; (void)out_size;
    const float* X     = (const float*)d_in[0];
    const int*   v_ids = (const int*)d_in[1];
    const int*   e_ids = (const int*)d_in[2];
    const float* Wq = (const float*)d_in[3];
    const float* bq = (const float*)d_in[4];
    const float* Wk = (const float*)d_in[5];
    const float* bk = (const float*)d_in[6];
    const float* Wv = (const float*)d_in[7];
    const float* bv = (const float*)d_in[8];
    const float* Wke = (const float*)d_in[9];
    const float* bke = (const float*)d_in[10];
    float* out = (float*)d_out;

    void *pXe, *pcnt, *pQKV, *pKe, *pQb, *pKeb;
    cudaGetSymbolAddress(&pXe, g_Xe);
    cudaGetSymbolAddress(&pcnt, g_cnt);
    cudaGetSymbolAddress(&pQKV, g_QKV);
    cudaGetSymbolAddress(&pKe, g_Ke);
    cudaGetSymbolAddress(&pQb, g_Qb);
    cudaGetSymbolAddress(&pKeb, g_Keb);

    cudaMemsetAsync(pXe, 0, (size_t)N_EDGES * C_DIM * sizeof(float));
    cudaMemsetAsync(pcnt, 0, (size_t)N_EDGES * sizeof(float));

    dim3 gq(N_NODES / 64, 4);
    gemm_bias_kernel<<<gq, 256>>>(X, Wq, bq, (float*)pQKV, 768, 0, (__nv_bfloat16*)pQb);
    gemm_bias_kernel<<<gq, 256>>>(X, Wk, bk, (float*)pQKV, 768, 256, nullptr);
    gemm_bias_kernel<<<gq, 256>>>(X, Wv, bv, (float*)pQKV, 768, 512, nullptr);

    seg_accum_kernel<<<(NNZ_P * 64) / 256, 256>>>(X, v_ids, e_ids);
    seg_finalize_kernel<<<(N_EDGES * 64) / 256, 256>>>();

    xe_transpose_kernel<<<dim3(N_EDGES / 64, C_DIM / 64), 256>>>();
    gemm_bias_kernel<<<dim3(N_EDGES / 64, 4), 256>>>((const float*)pXe, Wke, bke,
                                                     (float*)pKe, 256, 0,
                                                     (__nv_bfloat16*)pKeb);

    node_attn_kernel<<<(N_NODES * 32) / 256, 256>>>(out);

    cudaFuncSetAttribute(edge_attn_mma_kernel,
                         cudaFuncAttributeMaxDynamicSharedMemorySize, SMEM_ATT);
    edge_attn_mma_kernel<<<N_NODES / TM, 256, SMEM_ATT>>>(out);
}

// round 10
// speedup vs baseline: 7.5784x; 1.2940x over previous
#include <cuda_runtime.h>
#include <cuda_bf16.h>
#include <cstdint>

#define N_NODES 16384
#define N_EDGES 8192
#define C_DIM   256
#define NNZ_P   262144
#define SCALE   0.17677669529663687f   /* 1/sqrt(32) */

// ---------------- device scratch ----------------
__device__ float g_QKV[(size_t)N_NODES * 3 * C_DIM];   // rows of 768: Q|K|V (fp32)
__device__ float g_Xe[(size_t)N_EDGES * C_DIM];        // hyperedge mean features
__device__ float g_Ke[(size_t)N_EDGES * C_DIM];        // Xe @ Wke + bke (fp32)
__device__ __nv_bfloat16 g_Qb[(size_t)N_NODES * C_DIM];    // Q bf16 row-major
__device__ __nv_bfloat16 g_Keb[(size_t)N_EDGES * C_DIM];   // Ke bf16 row-major
__device__ __nv_bfloat16 g_XeTb[(size_t)C_DIM * N_EDGES];  // Xe^T bf16 [C][E]
// 3xbf16 GEMM operands
__device__ __nv_bfloat16 g_Xh[(size_t)N_NODES * C_DIM];
__device__ __nv_bfloat16 g_Xl[(size_t)N_NODES * C_DIM];
__device__ __nv_bfloat16 g_Xeh[(size_t)N_EDGES * C_DIM];
__device__ __nv_bfloat16 g_Xel[(size_t)N_EDGES * C_DIM];
__device__ __nv_bfloat16 g_Wt[4][2][C_DIM * C_DIM];    // [which][hi/lo][n][k]
// CSR for segment mean
__device__ int g_cnt_i[N_EDGES];
__device__ int g_cur[N_EDGES];
__device__ int g_off[N_EDGES];
__device__ int g_csr_v[NNZ_P];

// ================= helpers =================
__device__ __forceinline__ uint32_t smem_to_u32(const void* p) {
    uint32_t a;
    asm("{ .reg .u64 t; cvta.to.shared.u64 t, %1; cvt.u32.u64 %0, t; }" : "=r"(a) : "l"(p));
    return a;
}
#define CVT_BF16X2_F32(result, a, b) \
    asm("cvt.rn.satfinite.bf16x2.f32 %0, %1, %2;" : "=r"(result) : "f"(b), "f"(a))

__device__ __forceinline__ void cp16(uint32_t dst, const void* src) {
    asm volatile("cp.async.cg.shared.global [%0], [%1], 16;" :: "r"(dst), "l"(src));
}
#define CP_COMMIT() asm volatile("cp.async.commit_group;" ::: "memory")
#define CP_WAIT0()  asm volatile("cp.async.wait_group 0;" ::: "memory")
#define CP_WAIT1()  asm volatile("cp.async.wait_group 1;" ::: "memory")

__device__ __forceinline__ void ldsm4(uint32_t* r, uint32_t addr) {
    asm volatile("ldmatrix.sync.aligned.m8n8.x4.shared.b16 {%0,%1,%2,%3}, [%4];"
        : "=r"(r[0]), "=r"(r[1]), "=r"(r[2]), "=r"(r[3]) : "r"(addr));
}
__device__ __forceinline__ void mma16816(float* d, const uint32_t* a, uint32_t b0, uint32_t b1) {
    asm volatile("mma.sync.aligned.m16n8k16.row.col.f32.bf16.bf16.f32 "
        "{%0,%1,%2,%3}, {%4,%5,%6,%7}, {%8,%9}, {%0,%1,%2,%3};"
        : "+f"(d[0]), "+f"(d[1]), "+f"(d[2]), "+f"(d[3])
        : "r"(a[0]), "r"(a[1]), "r"(a[2]), "r"(a[3]), "r"(b0), "r"(b1));
}

// ---------------- fp32 -> bf16 hi/lo split (vectorized) ----------------
__global__ void __launch_bounds__(256)
split_hilo_kernel(const float* __restrict__ src, __nv_bfloat16* __restrict__ h,
                  __nv_bfloat16* __restrict__ l, int n4)
{
    int t = blockIdx.x * 256 + threadIdx.x;
    if (t >= n4) return;
    float4 x = ((const float4*)src)[t];
    float h0 = __bfloat162float(__float2bfloat16(x.x));
    float h1 = __bfloat162float(__float2bfloat16(x.y));
    float h2 = __bfloat162float(__float2bfloat16(x.z));
    float h3 = __bfloat162float(__float2bfloat16(x.w));
    uint32_t ha, hb, la, lb;
    CVT_BF16X2_F32(ha, h0, h1);
    CVT_BF16X2_F32(hb, h2, h3);
    CVT_BF16X2_F32(la, x.x - h0, x.y - h1);
    CVT_BF16X2_F32(lb, x.z - h2, x.w - h3);
    *(uint2*)(h + (size_t)t * 4) = make_uint2(ha, hb);
    *(uint2*)(l + (size_t)t * 4) = make_uint2(la, lb);
}

// ---------------- W[k][n] -> Wt[n][k] hi/lo bf16 ----------------
__global__ void __launch_bounds__(256)
wt_prep_kernel(const float* __restrict__ W, __nv_bfloat16* __restrict__ Th,
               __nv_bfloat16* __restrict__ Tl)
{
    __shared__ float t[64][65];
    int k0 = blockIdx.x * 64, n0 = blockIdx.y * 64;
    int tid = threadIdx.x;
#pragma unroll
    for (int it = 0; it < 4; it++) {
        int idx = it * 256 + tid;
        int k = idx >> 4, n4 = idx & 15;
        float4 v = *(const float4*)(W + (size_t)(k0 + k) * 256 + n0 + n4 * 4);
        t[k][n4 * 4 + 0] = v.x; t[k][n4 * 4 + 1] = v.y;
        t[k][n4 * 4 + 2] = v.z; t[k][n4 * 4 + 3] = v.w;
    }
    __syncthreads();
#pragma unroll
    for (int it = 0; it < 4; it++) {
        int idx = it * 256 + tid;
        int n = idx >> 4, k4 = idx & 15;
        float x0 = t[k4 * 4 + 0][n], x1 = t[k4 * 4 + 1][n];
        float x2 = t[k4 * 4 + 2][n], x3 = t[k4 * 4 + 3][n];
        float h0 = __bfloat162float(__float2bfloat16(x0));
        float h1 = __bfloat162float(__float2bfloat16(x1));
        float h2 = __bfloat162float(__float2bfloat16(x2));
        float h3 = __bfloat162float(__float2bfloat16(x3));
        uint32_t ha, hb, la, lb;
        CVT_BF16X2_F32(ha, h0, h1);
        CVT_BF16X2_F32(hb, h2, h3);
        CVT_BF16X2_F32(la, x0 - h0, x1 - h1);
        CVT_BF16X2_F32(lb, x2 - h2, x3 - h3);
        *(uint2*)(Th + (size_t)(n0 + n) * 256 + k0 + k4 * 4) = make_uint2(ha, hb);
        *(uint2*)(Tl + (size_t)(n0 + n) * 256 + k0 + k4 * 4) = make_uint2(la, lb);
    }
}

// ================= 3xbf16 tensor-core GEMM =================
// Out[m, coff+n] = A[m,:] @ W[:,n] + b[n];  A via (Ah+Al), W via (Bh+Bl) [n][k]
// block: 128 rows x 256 cols, K-steps of 32, double-buffered cp.async.
#define GST   40
#define GA_H  0
#define GA_L  10240
#define GB_H  20480
#define GB_L  40960
#define GBUF  61440
#define SMEM_GEMM (2 * GBUF)

__global__ void __launch_bounds__(256, 1)
mma_gemm3_kernel(const __nv_bfloat16* __restrict__ Ah, const __nv_bfloat16* __restrict__ Al,
                 const __nv_bfloat16* __restrict__ Bh, const __nv_bfloat16* __restrict__ Bl,
                 const float* __restrict__ bias, float* __restrict__ OutF,
                 int ldo, int coff, __nv_bfloat16* __restrict__ OutB)
{
    extern __shared__ char smg[];
    const uint32_t sb = smem_to_u32(smg);
    const int tid = threadIdx.x;
    const int lane = tid & 31;
    const int wid = tid >> 5;
    const int bm = blockIdx.x * 128;
    const int m0 = wid * 16;

    float acc[32][4];
#pragma unroll
    for (int i = 0; i < 32; i++)
#pragma unroll
        for (int q = 0; q < 4; q++) acc[i][q] = 0.f;

    // tile loader
#define LOAD_TILE(buf, k0) do { \
        uint32_t base_ = sb + (buf) * GBUF; \
        _Pragma("unroll") \
        for (int it = 0; it < 2; it++) { \
            int idx = it * 256 + tid; int r = idx >> 2, c = idx & 3; \
            uint32_t off = (uint32_t)(r * GST + c * 8) * 2; \
            cp16(base_ + GA_H + off, Ah + (size_t)(bm + r) * 256 + (k0) + c * 8); \
            cp16(base_ + GA_L + off, Al + (size_t)(bm + r) * 256 + (k0) + c * 8); \
        } \
        _Pragma("unroll") \
        for (int it = 0; it < 4; it++) { \
            int idx = it * 256 + tid; int n = idx >> 2, c = idx & 3; \
            uint32_t off = (uint32_t)(n * GST + c * 8) * 2; \
            cp16(base_ + GB_H + off, Bh + (size_t)n * 256 + (k0) + c * 8); \
            cp16(base_ + GB_L + off, Bl + (size_t)n * 256 + (k0) + c * 8); \
        } \
    } while (0)

    LOAD_TILE(0, 0);
    CP_COMMIT();

    const uint32_t a_rowoff = (uint32_t)((m0 + (lane & 15)) * GST + ((lane >> 4) << 3)) * 2;
    const uint32_t b_row = ((uint32_t)(lane >> 4) << 3) + (lane & 7);
    const uint32_t b_coloff = ((uint32_t)(lane >> 3) & 1) << 3;
    const uint32_t b_rowoff = (b_row * GST + b_coloff) * 2;

    for (int step = 0; step < 8; step++) {
        const int buf = step & 1;
        if (step < 7) {
            LOAD_TILE(buf ^ 1, (step + 1) * 32);
            CP_COMMIT();
            CP_WAIT1();
        } else {
            CP_WAIT0();
        }
        __syncthreads();

        const uint32_t ab_h = sb + buf * GBUF + GA_H + a_rowoff;
        const uint32_t ab_l = sb + buf * GBUF + GA_L + a_rowoff;
        const uint32_t bb_h = sb + buf * GBUF + GB_H + b_rowoff;
        const uint32_t bb_l = sb + buf * GBUF + GB_L + b_rowoff;
#pragma unroll
        for (int kc = 0; kc < 2; kc++) {
            uint32_t ah[4], al[4];
            ldsm4(ah, ab_h + kc * 32);
            ldsm4(al, ab_l + kc * 32);
#pragma unroll
            for (int ng = 0; ng < 16; ng++) {
                uint32_t bh[4], bl[4];
                ldsm4(bh, bb_h + (uint32_t)(ng * 16 * GST) * 2 + kc * 32);
                ldsm4(bl, bb_l + (uint32_t)(ng * 16 * GST) * 2 + kc * 32);
                mma16816(acc[2 * ng], ah, bh[0], bh[1]);
                mma16816(acc[2 * ng], ah, bl[0], bl[1]);
                mma16816(acc[2 * ng], al, bh[0], bh[1]);
                mma16816(acc[2 * ng + 1], ah, bh[2], bh[3]);
                mma16816(acc[2 * ng + 1], ah, bl[2], bl[3]);
                mma16816(acc[2 * ng + 1], al, bh[2], bh[3]);
            }
        }
        __syncthreads();
    }

    // epilogue
    const int g = lane >> 2;
    const int ti = lane & 3;
    const size_t r0 = (size_t)(bm + m0 + g);
    const size_t r1 = r0 + 8;
#pragma unroll
    for (int nt = 0; nt < 32; nt++) {
        int col = nt * 8 + ti * 2;
        float b0 = bias[col], b1 = bias[col + 1];
        float v00 = acc[nt][0] + b0, v01 = acc[nt][1] + b1;
        float v10 = acc[nt][2] + b0, v11 = acc[nt][3] + b1;
        *(float2*)(OutF + r0 * ldo + coff + col) = make_float2(v00, v01);
        *(float2*)(OutF + r1 * ldo + coff + col) = make_float2(v10, v11);
        if (OutB) {
            uint32_t p0, p1;
            CVT_BF16X2_F32(p0, v00, v01);
            CVT_BF16X2_F32(p1, v10, v11);
            *(uint32_t*)(OutB + r0 * 256 + col) = p0;
            *(uint32_t*)(OutB + r1 * 256 + col) = p1;
        }
    }
#undef LOAD_TILE
}

// ================= CSR segment mean =================
__global__ void __launch_bounds__(256)
hist_kernel(const int* __restrict__ e_ids)
{
    int t = blockIdx.x * 256 + threadIdx.x;
    if (t < NNZ_P) atomicAdd(&g_cnt_i[e_ids[t]], 1);
}

__global__ void __launch_bounds__(256)
scan_kernel()
{
    __shared__ int part[256];
    const int tid = threadIdx.x;
    const int base = tid * 32;
    int s = 0;
#pragma unroll
    for (int j = 0; j < 32; j++) s += g_cnt_i[base + j];
    part[tid] = s;
    __syncthreads();
    int acc = s;
#pragma unroll
    for (int off = 1; off < 256; off <<= 1) {
        int v = (tid >= off) ? part[tid - off] : 0;
        __syncthreads();
        acc += v;
        part[tid] = acc;
        __syncthreads();
    }
    int run = part[tid] - s;   // exclusive prefix
    for (int j = 0; j < 32; j++) {
        g_off[base + j] = run;
        run += g_cnt_i[base + j];
    }
}

__global__ void __launch_bounds__(256)
scatter_kernel(const int* __restrict__ v_ids, const int* __restrict__ e_ids)
{
    int t = blockIdx.x * 256 + threadIdx.x;
    if (t >= NNZ_P) return;
    int e = e_ids[t];
    int pos = atomicAdd(&g_cur[e], 1);
    g_csr_v[g_off[e] + pos] = v_ids[t];
}

__global__ void __launch_bounds__(256)
seg_reduce_kernel(const float* __restrict__ X)
{
    int w = (blockIdx.x * 256 + threadIdx.x) >> 5;
    int lane = threadIdx.x & 31;
    if (w >= N_EDGES) return;
    const int beg = g_off[w];
    const int deg = g_cnt_i[w];
    const float4* Xf = (const float4*)X;
    float4 a0 = make_float4(0.f, 0.f, 0.f, 0.f);
    float4 a1 = make_float4(0.f, 0.f, 0.f, 0.f);
    int j = 0;
    for (; j + 1 < deg; j += 2) {
        int v0 = g_csr_v[beg + j];
        int v1 = g_csr_v[beg + j + 1];
        float4 x0 = Xf[(size_t)v0 * 64 + lane];
        float4 y0 = Xf[(size_t)v0 * 64 + 32 + lane];
        float4 x1 = Xf[(size_t)v1 * 64 + lane];
        float4 y1 = Xf[(size_t)v1 * 64 + 32 + lane];
        a0.x += x0.x + x1.x; a0.y += x0.y + x1.y;
        a0.z += x0.z + x1.z; a0.w += x0.w + x1.w;
        a1.x += y0.x + y1.x; a1.y += y0.y + y1.y;
        a1.z += y0.z + y1.z; a1.w += y0.w + y1.w;
    }
    if (j < deg) {
        int v0 = g_csr_v[beg + j];
        float4 x0 = Xf[(size_t)v0 * 64 + lane];
        float4 y0 = Xf[(size_t)v0 * 64 + 32 + lane];
        a0.x += x0.x; a0.y += x0.y; a0.z += x0.z; a0.w += x0.w;
        a1.x += y0.x; a1.y += y0.y; a1.z += y0.z; a1.w += y0.w;
    }
    const float inv = 1.0f / (float)max(deg, 1);
    float4* dst = (float4*)(g_Xe + (size_t)w * 256);
    a0.x *= inv; a0.y *= inv; a0.z *= inv; a0.w *= inv;
    a1.x *= inv; a1.y *= inv; a1.z *= inv; a1.w *= inv;
    dst[lane] = a0;
    dst[lane + 32] = a1;
}

// ---------------- Xe transpose -> bf16 [C][E] ----------------
__global__ void __launch_bounds__(256)
xe_transpose_kernel()
{
    __shared__ float t[64][65];
    int e0 = blockIdx.x * 64;
    int c0 = blockIdx.y * 64;
    int tid = threadIdx.x;
#pragma unroll
    for (int it = 0; it < 4; it++) {
        int idx = it * 256 + tid;
        int e = idx >> 4;
        int c4 = idx & 15;
        float4 v = *(const float4*)(g_Xe + (size_t)(e0 + e) * 256 + c0 + c4 * 4);
        t[e][c4 * 4 + 0] = v.x; t[e][c4 * 4 + 1] = v.y;
        t[e][c4 * 4 + 2] = v.z; t[e][c4 * 4 + 3] = v.w;
    }
    __syncthreads();
#pragma unroll
    for (int it = 0; it < 4; it++) {
        int idx = it * 256 + tid;
        int c = idx >> 4;
        int e4 = idx & 15;
        uint32_t lo, hi;
        CVT_BF16X2_F32(lo, t[e4 * 4 + 0][c], t[e4 * 4 + 1][c]);
        CVT_BF16X2_F32(hi, t[e4 * 4 + 2][c], t[e4 * 4 + 3][c]);
        *(uint2*)(g_XeTb + (size_t)(c0 + c) * N_EDGES + e0 + e4 * 4) = make_uint2(lo, hi);
    }
}

// ---------------- per-node 8x8 head attention ----------------
__device__ __forceinline__ float warp_sum(float v) {
#pragma unroll
    for (int off = 16; off; off >>= 1) v += __shfl_xor_sync(0xffffffffu, v, off);
    return v;
}

__global__ void __launch_bounds__(256)
node_attn_kernel(float* __restrict__ out)
{
    int warp = (blockIdx.x * 256 + threadIdx.x) >> 5;
    int lane = threadIdx.x & 31;
    if (warp >= N_NODES) return;
    const float* row = g_QKV + (size_t)warp * 768;
    float q[8], k[8], v[8];
#pragma unroll
    for (int h = 0; h < 8; h++) {
        q[h] = row[h * 32 + lane];
        k[h] = row[256 + h * 32 + lane];
        v[h] = row[512 + h * 32 + lane];
    }
    float s[8][8];
#pragma unroll
    for (int h = 0; h < 8; h++)
#pragma unroll
        for (int g = 0; g < 8; g++)
            s[h][g] = warp_sum(q[h] * k[g]) * SCALE;

#pragma unroll
    for (int h = 0; h < 8; h++) {
        float m = s[h][0];
#pragma unroll
        for (int g = 1; g < 8; g++) m = fmaxf(m, s[h][g]);
        float sum = 0.f;
#pragma unroll
        for (int g = 0; g < 8; g++) { s[h][g] = __expf(s[h][g] - m); sum += s[h][g]; }
        float inv = 1.0f / sum;
        float o = 0.f;
#pragma unroll
        for (int g = 0; g < 8; g++) o = fmaf(s[h][g] * inv, v[g], o);
        out[(size_t)warp * 256 + h * 32 + lane] = o;
    }
}

// ================= mma.sync bf16 flash attention over hyperedges ===========
#define TM    128
#define TN    64
#define NITER (N_EDGES / TN)
#define QST   264
#define KST   264
#define VST   72
#define SM_Q  0
#define SM_K0 67584
#define SM_K1 (SM_K0 + 33792)
#define SM_V0 (SM_K1 + 33792)
#define SM_V1 (SM_V0 + 36864)
#define SMEM_ATT (SM_V1 + 36864)

__global__ void __launch_bounds__(256, 1)
edge_attn_mma_kernel(float* __restrict__ out)
{
    extern __shared__ char sm[];
    const uint32_t smem_base = smem_to_u32(sm);
    const int tid  = threadIdx.x;
    const int lane = tid & 31;
    const int wid  = tid >> 5;
    const int n0   = blockIdx.x * TM;
    const int m0   = wid * 16;

#pragma unroll
    for (int it = 0; it < 16; it++) {
        int idx = it * 256 + tid;
        int r = idx >> 5, ch = idx & 31;
        cp16(smem_base + SM_Q + (uint32_t)(r * QST + ch * 8) * 2,
             g_Qb + (size_t)(n0 + r) * 256 + ch * 8);
    }
#pragma unroll
    for (int it = 0; it < 8; it++) {
        int idx = it * 256 + tid;
        int e = idx >> 5, ch = idx & 31;
        cp16(smem_base + SM_K0 + (uint32_t)(e * KST + ch * 8) * 2,
             g_Keb + (size_t)e * 256 + ch * 8);
        int c = idx >> 3, vch = idx & 7;
        cp16(smem_base + SM_V0 + (uint32_t)(c * VST + vch * 8) * 2,
             g_XeTb + (size_t)c * N_EDGES + vch * 8);
    }
    CP_COMMIT();
    CP_WAIT0();
    __syncthreads();

    const uint32_t a_base = smem_base + SM_Q +
        (uint32_t)((m0 + (lane & 15)) * QST + ((lane >> 4) << 3)) * 2;
    const uint32_t b_row    = (uint32_t)(((lane >> 4) << 3) + (lane & 7));
    const uint32_t b_coloff = (uint32_t)(((lane >> 3) & 1) << 3);
    const uint32_t kfrag_base[2] = {
        smem_base + SM_K0 + (b_row * KST + b_coloff) * 2,
        smem_base + SM_K1 + (b_row * KST + b_coloff) * 2 };
    const uint32_t vfrag_base[2] = {
        smem_base + SM_V0 + (b_row * VST + b_coloff) * 2,
        smem_base + SM_V1 + (b_row * VST + b_coloff) * 2 };

    float O[32][4];
#pragma unroll
    for (int j = 0; j < 32; j++)
#pragma unroll
        for (int q = 0; q < 4; q++) O[j][q] = 0.f;
    float lacc0 = 0.f, lacc1 = 0.f;

    for (int i = 0; i < NITER; i++) {
        const int b = i & 1;
        if (i + 1 < NITER) {
            const int e0n = (i + 1) * TN;
            const uint32_t kb = smem_base + (b ? SM_K0 : SM_K1);
            const uint32_t vb = smem_base + (b ? SM_V0 : SM_V1);
#pragma unroll
            for (int it = 0; it < 8; it++) {
                int idx = it * 256 + tid;
                int e = idx >> 5, ch = idx & 31;
                cp16(kb + (uint32_t)(e * KST + ch * 8) * 2,
                     g_Keb + (size_t)(e0n + e) * 256 + ch * 8);
                int c = idx >> 3, vch = idx & 7;
                cp16(vb + (uint32_t)(c * VST + vch * 8) * 2,
                     g_XeTb + (size_t)c * N_EDGES + e0n + vch * 8);
            }
            CP_COMMIT();
        }

        float s[8][4];
#pragma unroll
        for (int j = 0; j < 8; j++)
#pragma unroll
            for (int q = 0; q < 4; q++) s[j][q] = 0.f;
        const uint32_t kb_ = kfrag_base[b];
#pragma unroll
        for (int k0 = 0; k0 < 256; k0 += 16) {
            uint32_t a[4];
            ldsm4(a, a_base + (uint32_t)k0 * 2);
#pragma unroll
            for (int jp = 0; jp < 4; jp++) {
                uint32_t bb[4];
                ldsm4(bb, kb_ + (uint32_t)(jp * 16 * KST + k0) * 2);
                mma16816(s[2 * jp],     a, bb[0], bb[1]);
                mma16816(s[2 * jp + 1], a, bb[2], bb[3]);
            }
        }

        float part0 = 0.f, part1 = 0.f;
#pragma unroll
        for (int j = 0; j < 8; j++) {
            s[j][0] = __expf(s[j][0] * SCALE);
            s[j][1] = __expf(s[j][1] * SCALE);
            s[j][2] = __expf(s[j][2] * SCALE);
            s[j][3] = __expf(s[j][3] * SCALE);
            part0 += s[j][0] + s[j][1];
            part1 += s[j][2] + s[j][3];
        }
        part0 += __shfl_xor_sync(0xffffffffu, part0, 1);
        part0 += __shfl_xor_sync(0xffffffffu, part0, 2);
        part1 += __shfl_xor_sync(0xffffffffu, part1, 1);
        part1 += __shfl_xor_sync(0xffffffffu, part1, 2);
        lacc0 += part0;
        lacc1 += part1;

        const uint32_t vb_ = vfrag_base[b];
#pragma unroll
        for (int kb = 0; kb < 4; kb++) {
            uint32_t a[4];
            CVT_BF16X2_F32(a[0], s[2 * kb][0],     s[2 * kb][1]);
            CVT_BF16X2_F32(a[1], s[2 * kb][2],     s[2 * kb][3]);
            CVT_BF16X2_F32(a[2], s[2 * kb + 1][0], s[2 * kb + 1][1]);
            CVT_BF16X2_F32(a[3], s[2 * kb + 1][2], s[2 * kb + 1][3]);
#pragma unroll
            for (int jp = 0; jp < 16; jp++) {
                uint32_t bb[4];
                ldsm4(bb, vb_ + (uint32_t)(jp * 16 * VST + kb * 16) * 2);
                mma16816(O[2 * jp],     a, bb[0], bb[1]);
                mma16816(O[2 * jp + 1], a, bb[2], bb[3]);
            }
        }

        if (i + 1 < NITER) CP_WAIT0();
        __syncthreads();
    }

    const int g = lane >> 2;
    const int ti = lane & 3;
    const float inv0 = 1.0f / lacc0;
    const float inv1 = 1.0f / lacc1;
    const size_t row0 = (size_t)(n0 + m0 + g);
    const size_t row1 = row0 + 8;
#pragma unroll
    for (int j = 0; j < 32; j++) {
        int col = 8 * j + 2 * ti;
        float2* p0 = (float2*)(out + row0 * 256 + col);
        float2 v0 = *p0;
        v0.x = fmaxf(v0.x + O[j][0] * inv0, 0.f);
        v0.y = fmaxf(v0.y + O[j][1] * inv0, 0.f);
        *p0 = v0;
        float2* p1 = (float2*)(out + row1 * 256 + col);
        float2 v1 = *p1;
        v1.x = fmaxf(v1.x + O[j][2] * inv1, 0.f);
        v1.y = fmaxf(v1.y + O[j][3] * inv1, 0.f);
        *p1 = v1;
    }
}

// ---------------- launch ----------------
extern "C" void kernel_launch(void* const* d_in, const int* in_sizes, int n_in,
                              void* d_out, int out_size)
{
    (void)in_sizes; (void)n_in; (void)out_size;
    const float* X     = (const float*)d_in[0];
    const int*   v_ids = (const int*)d_in[1];
    const int*   e_ids = (const int*)d_in[2];
    const float* Wq = (const float*)d_in[3];
    const float* bq = (const float*)d_in[4];
    const float* Wk = (const float*)d_in[5];
    const float* bk = (const float*)d_in[6];
    const float* Wv = (const float*)d_in[7];
    const float* bv = (const float*)d_in[8];
    const float* Wke = (const float*)d_in[9];
    const float* bke = (const float*)d_in[10];
    float* out = (float*)d_out;

    void *pQKV, *pKe, *pQb, *pKeb, *pXe;
    void *pXh, *pXl, *pXeh, *pXel, *pWt, *pCnt, *pCur;
    cudaGetSymbolAddress(&pQKV, g_QKV);
    cudaGetSymbolAddress(&pKe, g_Ke);
    cudaGetSymbolAddress(&pQb, g_Qb);
    cudaGetSymbolAddress(&pKeb, g_Keb);
    cudaGetSymbolAddress(&pXe, g_Xe);
    cudaGetSymbolAddress(&pXh, g_Xh);
    cudaGetSymbolAddress(&pXl, g_Xl);
    cudaGetSymbolAddress(&pXeh, g_Xeh);
    cudaGetSymbolAddress(&pXel, g_Xel);
    cudaGetSymbolAddress(&pWt, g_Wt);
    cudaGetSymbolAddress(&pCnt, g_cnt_i);
    cudaGetSymbolAddress(&pCur, g_cur);

    __nv_bfloat16* Wt = (__nv_bfloat16*)pWt;
    const size_t WSZ = (size_t)C_DIM * C_DIM;

    cudaMemsetAsync(pCnt, 0, N_EDGES * sizeof(int));
    cudaMemsetAsync(pCur, 0, N_EDGES * sizeof(int));

    // CSR segment mean
    hist_kernel<<<NNZ_P / 256, 256>>>(e_ids);
    scan_kernel<<<1, 256>>>();
    scatter_kernel<<<NNZ_P / 256, 256>>>(v_ids, e_ids);
    seg_reduce_kernel<<<(N_EDGES * 32) / 256, 256>>>(X);

    // operand prep
    split_hilo_kernel<<<(N_NODES * 64) / 256, 256>>>(X, (__nv_bfloat16*)pXh,
                                                     (__nv_bfloat16*)pXl, N_NODES * 64);
    split_hilo_kernel<<<(N_EDGES * 64) / 256, 256>>>((const float*)pXe,
                                                     (__nv_bfloat16*)pXeh,
                                                     (__nv_bfloat16*)pXel, N_EDGES * 64);
    dim3 wg(4, 4);
    wt_prep_kernel<<<wg, 256>>>(Wq,  Wt + 0 * 2 * WSZ, Wt + (0 * 2 + 1) * WSZ);
    wt_prep_kernel<<<wg, 256>>>(Wk,  Wt + 1 * 2 * WSZ, Wt + (1 * 2 + 1) * WSZ);
    wt_prep_kernel<<<wg, 256>>>(Wv,  Wt + 2 * 2 * WSZ, Wt + (2 * 2 + 1) * WSZ);
    wt_prep_kernel<<<wg, 256>>>(Wke, Wt + 3 * 2 * WSZ, Wt + (3 * 2 + 1) * WSZ);

    xe_transpose_kernel<<<dim3(N_EDGES / 64, C_DIM / 64), 256>>>();

    // tensor-core GEMMs
    cudaFuncSetAttribute(mma_gemm3_kernel,
                         cudaFuncAttributeMaxDynamicSharedMemorySize, SMEM_GEMM);
    mma_gemm3_kernel<<<N_NODES / 128, 256, SMEM_GEMM>>>(
        (const __nv_bfloat16*)pXh, (const __nv_bfloat16*)pXl,
        Wt + 0 * 2 * WSZ, Wt + (0 * 2 + 1) * WSZ, bq,
        (float*)pQKV, 768, 0, (__nv_bfloat16*)pQb);
    mma_gemm3_kernel<<<N_NODES / 128, 256, SMEM_GEMM>>>(
        (const __nv_bfloat16*)pXh, (const __nv_bfloat16*)pXl,
        Wt + 1 * 2 * WSZ, Wt + (1 * 2 + 1) * WSZ, bk,
        (float*)pQKV, 768, 256, nullptr);
    mma_gemm3_kernel<<<N_NODES / 128, 256, SMEM_GEMM>>>(
        (const __nv_bfloat16*)pXh, (const __nv_bfloat16*)pXl,
        Wt + 2 * 2 * WSZ, Wt + (2 * 2 + 1) * WSZ, bv,
        (float*)pQKV, 768, 512, nullptr);
    mma_gemm3_kernel<<<N_EDGES / 128, 256, SMEM_GEMM>>>(
        (const __nv_bfloat16*)pXeh, (const __nv_bfloat16*)pXel,
        Wt + 3 * 2 * WSZ, Wt + (3 * 2 + 1) * WSZ, bke,
        (float*)pKe, 256, 0, (__nv_bfloat16*)pKeb);

    node_attn_kernel<<<(N_NODES * 32) / 256, 256>>>(out);

    cudaFuncSetAttribute(edge_attn_mma_kernel,
                         cudaFuncAttributeMaxDynamicSharedMemorySize, SMEM_ATT);
    edge_attn_mma_kernel<<<N_NODES / TM, 256, SMEM_ATT>>>(out);
}